// round 8
// baseline (speedup 1.0000x reference)
#include <cuda_runtime.h>
#include <cstdint>

// FerroelectricBasisConv2d — GB300 sm_103a, round 8
//   g  = tanh(5x+5Ec)  ~= a(1+A1 t)/(1+B1 t+B2 t^2), t=a^2, a=clamp(5x+5Ec,±4)
//        (rational fit max err 8e-4; division via magic-rcp + 1 Newton, err<=2.6e-3)
//   u  = k*x + 0.9kEc + 0.1kEc*g ;  out = sum w*tanh(u) + sum(bias*coef) + out_bias
// Gate entirely on FMA/ALU pipes, packed f32x2 (pair cin c with c+8).
// MUFU/term: 10.7 (outer tanh only; was 21.4 = round-4 floor 34.7us)

#define CIN     16
#define COUT    32
#define HW      32
#define NT      432
#define NPAIR   216
#define TILE_H  8
#define TILE_W  16
#define RG_H    10
#define RG_W    18
#define THREADS 128

typedef unsigned long long ull;

__device__ __forceinline__ float tanh_fast(float x) {
    float r; asm("tanh.approx.f32 %0, %1;" : "=f"(r) : "f"(x)); return r;
}
__device__ __forceinline__ ull f2_fma(ull a, ull b, ull c) {
    ull d; asm("fma.rn.f32x2 %0, %1, %2, %3;" : "=l"(d) : "l"(a), "l"(b), "l"(c)); return d;
}
__device__ __forceinline__ ull f2_mul(ull a, ull b) {
    ull d; asm("mul.rn.f32x2 %0, %1, %2;" : "=l"(d) : "l"(a), "l"(b)); return d;
}
__device__ __forceinline__ ull f2_pack(float lo, float hi) {
    ull d; asm("mov.b64 %0, {%1, %2};" : "=l"(d) : "f"(lo), "f"(hi)); return d;
}
__device__ __forceinline__ void f2_unpack(ull v, float& lo, float& hi) {
    asm("mov.b64 {%0, %1}, %2;" : "=f"(lo), "=f"(hi) : "l"(v));
}

// rational gate coefficients (fit verified: |err| <= 8e-4 on [-4,4])
#define GA1 0.0837500f
#define GB1 0.4158160f
#define GB2 0.0066923f

__global__ __launch_bounds__(THREADS, 5)
void ferro_kernel(const float* __restrict__ x,
                  const float* __restrict__ k,
                  const float* __restrict__ Ec,
                  const float* __restrict__ Ps,
                  const float* __restrict__ bias,
                  const float* __restrict__ coef,
                  const float* __restrict__ out_bias,
                  float* __restrict__ out)
{
    __shared__ float2 fe[NPAIR];   // {5Ec_j, 5Ec_j+216}
    __shared__ float2 fk[NPAIR];   // {k, k'}
    __shared__ float2 fb[NPAIR];   // {0.9kEc, .}
    __shared__ float2 fc[NPAIR];   // {-0.1kEc, .}
    __shared__ float2 fw[NPAIR];   // {Ps*coef, .}
    __shared__ float  xs[CIN * RG_H * RG_W];
    __shared__ float  red[THREADS];

    const int tid = threadIdx.x;
    const int bx  = blockIdx.x;
    const int sub = bx & 7;
    const int sy  = sub >> 1, sx = sub & 1;
    const int co  = (bx >> 3) & 31;
    const int b   = bx >> 8;
    const int oy0 = sy * TILE_H, ox0 = sx * TILE_W;

    const float* kp  = k    + co * NT;
    const float* ep  = Ec   + co * NT;
    const float* pp  = Ps   + co * NT;
    const float* bp  = bias + co * NT;
    const float* cp  = coef + co * NT;

    float part = 0.0f;
    for (int j = tid; j < NPAIR; j += THREADS) {
        int j1 = j + NPAIR;
        float k0 = kp[j],  e0 = ep[j],  k1 = kp[j1], e1 = ep[j1];
        float ke0 = k0 * e0, ke1 = k1 * e1;
        fe[j] = make_float2(5.0f * e0, 5.0f * e1);
        fk[j] = make_float2(k0, k1);
        fb[j] = make_float2(0.9f * ke0, 0.9f * ke1);
        fc[j] = make_float2(-0.1f * ke0, -0.1f * ke1);
        fw[j] = make_float2(pp[j] * cp[j], pp[j1] * cp[j1]);
        part += bp[j] * cp[j] + bp[j1] * cp[j1];
    }
    red[tid] = part;

    for (int i = tid; i < CIN * RG_H * RG_W; i += THREADS) {
        int cin = i / (RG_H * RG_W);
        int rem = i - cin * (RG_H * RG_W);
        int r   = rem / RG_W;
        int c   = rem - r * RG_W;
        int gy  = oy0 - 1 + r;
        int gx  = ox0 - 1 + c;
        float v = 0.0f;
        if ((unsigned)gy < (unsigned)HW && (unsigned)gx < (unsigned)HW)
            v = x[((b * CIN + cin) * HW + gy) * HW + gx];
        xs[i] = v;
    }
    __syncthreads();

    #pragma unroll
    for (int s = THREADS / 2; s > 0; s >>= 1) {
        if (tid < s) red[tid] += red[tid + s];
        __syncthreads();
    }

    const int ty = tid >> 4;
    const int tx = tid & 15;

    float acc0 = red[0] + __ldg(out_bias + co);
    float acc1 = 0.0f;

    const ull FIVE2 = f2_pack(5.0f, 5.0f);
    const ull ONE2  = f2_pack(1.0f, 1.0f);
    const ull A12   = f2_pack(GA1, GA1);
    const ull B12   = f2_pack(GB1, GB1);
    const ull B22   = f2_pack(GB2, GB2);
    const ull MTWO2 = f2_pack(-2.0f, -2.0f);

    for (int c = 0; c < 8; ++c) {
        const float* xb0 = xs + c * (RG_H * RG_W) + ty * RG_W + tx;
        const float* xb1 = xb0 + 8 * (RG_H * RG_W);
        const int jb = c * 27;
        #pragma unroll
        for (int kh = 0; kh < 3; ++kh) {
            #pragma unroll
            for (int kw = 0; kw < 3; ++kw) {
                const float xv0 = xb0[kh * RG_W + kw];
                const float xv1 = xb1[kh * RG_W + kw];
                const ull x2 = f2_pack(xv0, xv1);
                const int tap = kh * 3 + kw;
                #pragma unroll
                for (int kkk = 0; kkk < 3; ++kkk) {
                    const int j = jb + kkk * 9 + tap;
                    ull e2  = *reinterpret_cast<const ull*>(&fe[j]);
                    ull k2  = *reinterpret_cast<const ull*>(&fk[j]);
                    ull b2  = *reinterpret_cast<const ull*>(&fb[j]);
                    ull cn2 = *reinterpret_cast<const ull*>(&fc[j]);
                    float2 wv = fw[j];

                    // a = clamp(5x + 5Ec, -4, 4)
                    ull a2 = f2_fma(x2, FIVE2, e2);
                    float al, ah; f2_unpack(a2, al, ah);
                    al = fminf(fmaxf(al, -4.0f), 4.0f);
                    ah = fminf(fmaxf(ah, -4.0f), 4.0f);
                    ull acl = f2_pack(al, ah);

                    // rational: num = a(1+A1 t); den = 1 + t(B1 + B2 t)
                    ull t2   = f2_mul(acl, acl);
                    ull p2   = f2_fma(t2, A12, ONE2);
                    ull num2 = f2_mul(acl, p2);
                    ull q2   = f2_fma(t2, B22, B12);
                    ull d2   = f2_fma(t2, q2, ONE2);

                    // -1/den via magic + 1 Newton (den in [1, 9.4])
                    float dl, dh; f2_unpack(d2, dl, dh);
                    float rl = __uint_as_float(0x7EF127EAu - __float_as_uint(dl));
                    float rh = __uint_as_float(0x7EF127EAu - __float_as_uint(dh));
                    ull r0 = f2_pack(rl, rh);
                    ull m2 = f2_fma(d2, r0, MTWO2);   // d*r0 - 2
                    ull rn = f2_mul(r0, m2);          // -r0*(2 - d*r0) ~= -1/d

                    ull gn2   = f2_mul(num2, rn);     // -g
                    ull base2 = f2_fma(k2, x2, b2);   // k*x + 0.9kEc
                    ull u2    = f2_fma(cn2, gn2, base2); // + 0.1kEc*g

                    float u0, u1; f2_unpack(u2, u0, u1);
                    acc0 = fmaf(wv.x, tanh_fast(u0), acc0);
                    acc1 = fmaf(wv.y, tanh_fast(u1), acc1);
                }
            }
        }
    }

    const int oy = oy0 + ty, ox = ox0 + tx;
    out[((b * COUT + co) * HW + oy) * HW + ox] = acc0 + acc1;
}

extern "C" void kernel_launch(void* const* d_in, const int* in_sizes, int n_in,
                              void* d_out, int out_size)
{
    const float* x        = (const float*)d_in[0];
    const float* k        = (const float*)d_in[1];
    const float* Ec       = (const float*)d_in[2];
    const float* Ps       = (const float*)d_in[3];
    const float* bias     = (const float*)d_in[4];
    const float* coef     = (const float*)d_in[5];
    const float* out_bias = (const float*)d_in[6];
    float* out = (float*)d_out;

    ferro_kernel<<<4 * 32 * 8, THREADS>>>(x, k, Ec, Ps, bias, coef, out_bias, out);
}

// round 9
// speedup vs baseline: 1.1406x; 1.1406x over previous
#include <cuda_runtime.h>
#include <cstdint>

// FerroelectricBasisConv2d — GB300 sm_103a, round 9
// Hybrid pipe-balanced gate:
//   kkk==0  : g via MUFU tanh.approx (MUFU has slack)
//   kkk==1,2: g via packed-f32x2 rational a(1+A1t)/(1+B1t+B2t^2), magic-rcp+Newton
// Outer tanh always MUFU. u = k*x + 0.9kEc ± 0.1kEc*(±g).
// MUFU/pair = 2.667 (was 4.0 in r4-floor, 2.0-but-issue-bound in r8)

#define CIN     16
#define COUT    32
#define HW      32
#define NT      432
#define NPAIR   216
#define TILE_H  8
#define TILE_W  16
#define RG_H    10
#define RG_W    18
#define THREADS 128

typedef unsigned long long ull;

__device__ __forceinline__ float tanh_fast(float x) {
    float r; asm("tanh.approx.f32 %0, %1;" : "=f"(r) : "f"(x)); return r;
}
__device__ __forceinline__ ull f2_fma(ull a, ull b, ull c) {
    ull d; asm("fma.rn.f32x2 %0, %1, %2, %3;" : "=l"(d) : "l"(a), "l"(b), "l"(c)); return d;
}
__device__ __forceinline__ ull f2_mul(ull a, ull b) {
    ull d; asm("mul.rn.f32x2 %0, %1, %2;" : "=l"(d) : "l"(a), "l"(b)); return d;
}
__device__ __forceinline__ ull f2_pack(float lo, float hi) {
    ull d; asm("mov.b64 %0, {%1, %2};" : "=l"(d) : "f"(lo), "f"(hi)); return d;
}
__device__ __forceinline__ void f2_unpack(ull v, float& lo, float& hi) {
    asm("mov.b64 {%0, %1}, %2;" : "=f"(lo), "=f"(hi) : "l"(v));
}

// rational gate coefficients (|err| <= 8e-4 on [-4,4])
#define GA1 0.0837500f
#define GB1 0.4158160f
#define GB2 0.0066923f

__global__ __launch_bounds__(THREADS, 5)
void ferro_kernel(const float* __restrict__ x,
                  const float* __restrict__ k,
                  const float* __restrict__ Ec,
                  const float* __restrict__ Ps,
                  const float* __restrict__ bias,
                  const float* __restrict__ coef,
                  const float* __restrict__ out_bias,
                  float* __restrict__ out)
{
    __shared__ float4 P1[NPAIR];   // {5Ec0, 5Ec1, k0, k1}
    __shared__ float4 P2[NPAIR];   // {0.9kEc0, 0.9kEc1, sc*0.1kEc0, sc*0.1kEc1}  sc=+1 if kkk==0 else -1
    __shared__ float2 FW[NPAIR];   // {Ps*coef 0, Ps*coef 1}
    __shared__ float  xs[CIN * RG_H * RG_W];
    __shared__ float  red[THREADS];

    const int tid = threadIdx.x;
    const int bx  = blockIdx.x;
    const int sub = bx & 7;
    const int sy  = sub >> 1, sx = sub & 1;
    const int co  = (bx >> 3) & 31;
    const int b   = bx >> 8;
    const int oy0 = sy * TILE_H, ox0 = sx * TILE_W;

    const float* kp  = k    + co * NT;
    const float* ep  = Ec   + co * NT;
    const float* pp  = Ps   + co * NT;
    const float* bp  = bias + co * NT;
    const float* cp  = coef + co * NT;

    float part = 0.0f;
    for (int j = tid; j < NPAIR; j += THREADS) {
        int j1 = j + NPAIR;
        float k0 = kp[j],  e0 = ep[j],  k1 = kp[j1], e1 = ep[j1];
        float ke0 = k0 * e0, ke1 = k1 * e1;
        int kkk = (j % 27) / 9;
        float sc = (kkk == 0) ? 0.1f : -0.1f;   // rational path yields -g
        P1[j] = make_float4(5.0f * e0, 5.0f * e1, k0, k1);
        P2[j] = make_float4(0.9f * ke0, 0.9f * ke1, sc * ke0, sc * ke1);
        FW[j] = make_float2(pp[j] * cp[j], pp[j1] * cp[j1]);
        part += bp[j] * cp[j] + bp[j1] * cp[j1];
    }
    red[tid] = part;

    for (int i = tid; i < CIN * RG_H * RG_W; i += THREADS) {
        int cin = i / (RG_H * RG_W);
        int rem = i - cin * (RG_H * RG_W);
        int r   = rem / RG_W;
        int c   = rem - r * RG_W;
        int gy  = oy0 - 1 + r;
        int gx  = ox0 - 1 + c;
        float v = 0.0f;
        if ((unsigned)gy < (unsigned)HW && (unsigned)gx < (unsigned)HW)
            v = x[((b * CIN + cin) * HW + gy) * HW + gx];
        xs[i] = v;
    }
    __syncthreads();

    #pragma unroll
    for (int s = THREADS / 2; s > 0; s >>= 1) {
        if (tid < s) red[tid] += red[tid + s];
        __syncthreads();
    }

    const int ty = tid >> 4;
    const int tx = tid & 15;

    float acc0 = red[0] + __ldg(out_bias + co);
    float acc1 = 0.0f;

    const ull FIVE2 = f2_pack(5.0f, 5.0f);
    const ull ONE2  = f2_pack(1.0f, 1.0f);
    const ull A12   = f2_pack(GA1, GA1);
    const ull B12   = f2_pack(GB1, GB1);
    const ull B22   = f2_pack(GB2, GB2);
    const ull MTWO2 = f2_pack(-2.0f, -2.0f);

    for (int c = 0; c < 8; ++c) {
        const float* xb0 = xs + c * (RG_H * RG_W) + ty * RG_W + tx;
        const float* xb1 = xb0 + 8 * (RG_H * RG_W);
        const int jb = c * 27;
        #pragma unroll
        for (int kh = 0; kh < 3; ++kh) {
            #pragma unroll
            for (int kw = 0; kw < 3; ++kw) {
                const float xv0 = xb0[kh * RG_W + kw];
                const float xv1 = xb1[kh * RG_W + kw];
                const ull x2 = f2_pack(xv0, xv1);
                const int tap = kh * 3 + kw;
                #pragma unroll
                for (int kkk = 0; kkk < 3; ++kkk) {
                    const int j = jb + kkk * 9 + tap;
                    float4 p1 = P1[j];
                    float4 p2 = P2[j];
                    float2 wv = FW[j];
                    if (kkk == 0) {
                        // MUFU gate branch (pipe with slack)
                        float g0 = tanh_fast(fmaf(5.0f, xv0, p1.x));
                        float g1 = tanh_fast(fmaf(5.0f, xv1, p1.y));
                        float u0 = fmaf(p2.z, g0, fmaf(p1.z, xv0, p2.x));
                        float u1 = fmaf(p2.w, g1, fmaf(p1.w, xv1, p2.y));
                        acc0 = fmaf(wv.x, tanh_fast(u0), acc0);
                        acc1 = fmaf(wv.y, tanh_fast(u1), acc1);
                    } else {
                        // packed rational gate branch (fma/alu pipes)
                        ull e2  = f2_pack(p1.x, p1.y);
                        ull k2  = f2_pack(p1.z, p1.w);
                        ull b2  = f2_pack(p2.x, p2.y);
                        ull cn2 = f2_pack(p2.z, p2.w);      // -0.1kEc

                        ull a2 = f2_fma(x2, FIVE2, e2);
                        float al, ah; f2_unpack(a2, al, ah);
                        al = fminf(fmaxf(al, -4.0f), 4.0f);
                        ah = fminf(fmaxf(ah, -4.0f), 4.0f);
                        ull acl = f2_pack(al, ah);

                        ull t2   = f2_mul(acl, acl);
                        ull pp2  = f2_fma(t2, A12, ONE2);
                        ull num2 = f2_mul(acl, pp2);
                        ull q2   = f2_fma(t2, B22, B12);
                        ull d2   = f2_fma(t2, q2, ONE2);

                        float dl, dh; f2_unpack(d2, dl, dh);
                        float rl = __uint_as_float(0x7EF127EAu - __float_as_uint(dl));
                        float rh = __uint_as_float(0x7EF127EAu - __float_as_uint(dh));
                        ull r0 = f2_pack(rl, rh);
                        ull m2 = f2_fma(d2, r0, MTWO2);     // d*r0 - 2
                        ull rn = f2_mul(r0, m2);            // -1/d

                        ull gn2   = f2_mul(num2, rn);       // -g
                        ull base2 = f2_fma(k2, x2, b2);
                        ull u2    = f2_fma(cn2, gn2, base2);

                        float u0, u1; f2_unpack(u2, u0, u1);
                        acc0 = fmaf(wv.x, tanh_fast(u0), acc0);
                        acc1 = fmaf(wv.y, tanh_fast(u1), acc1);
                    }
                }
            }
        }
    }

    const int oy = oy0 + ty, ox = ox0 + tx;
    out[((b * COUT + co) * HW + oy) * HW + ox] = acc0 + acc1;
}

extern "C" void kernel_launch(void* const* d_in, const int* in_sizes, int n_in,
                              void* d_out, int out_size)
{
    const float* x        = (const float*)d_in[0];
    const float* k        = (const float*)d_in[1];
    const float* Ec       = (const float*)d_in[2];
    const float* Ps       = (const float*)d_in[3];
    const float* bias     = (const float*)d_in[4];
    const float* coef     = (const float*)d_in[5];
    const float* out_bias = (const float*)d_in[6];
    float* out = (float*)d_out;

    ferro_kernel<<<4 * 32 * 8, THREADS>>>(x, k, Ec, Ps, bias, coef, out_bias, out);
}